// round 3
// baseline (speedup 1.0000x reference)
#include <cuda_runtime.h>

#define BB 32
#define CC 448
#define HWI 32
#define PIN 1024       // 32*32
#define HWF 64
#define NPOS 4096
#define DP 100
#define DPAD 104
#define OHW 256

// ---- packed f32x2 helpers (sm_103a) ----
__device__ __forceinline__ unsigned long long pack2(float lo, float hi) {
    unsigned long long r;
    asm("mov.b64 %0, {%1, %2};" : "=l"(r) : "f"(lo), "f"(hi));
    return r;
}
__device__ __forceinline__ float2 unpack2(unsigned long long v) {
    float lo, hi;
    asm("mov.b64 {%0, %1}, %2;" : "=f"(lo), "=f"(hi) : "l"(v));
    return make_float2(lo, hi);
}
__device__ __forceinline__ unsigned long long fma2(unsigned long long a,
                                                   unsigned long long b,
                                                   unsigned long long c) {
    unsigned long long d;
    asm("fma.rn.f32x2 %0, %1, %2, %3;" : "=l"(d) : "l"(a), "l"(b), "l"(c));
    return d;
}
__device__ __forceinline__ void cpa16(unsigned int saddr, const void* g) {
    asm volatile("cp.async.ca.shared.global [%0], [%1], 16;\n" :: "r"(saddr), "l"(g));
}

// ---- scratch (static device globals; no allocation) ----
__device__ float g_WT[CC * DPAD];          // [c][d], zero-padded d>=100
__device__ float g_meanT[NPOS * DP];       // [n][c]
__device__ float g_proj[(size_t)BB * PIN * DP];  // [b][p][d]  (13.1 MB)
__device__ float g_dist[(size_t)BB * NPOS];      // [b][n]

// ---------------------------------------------------------------------------
// prep_w: proj_w [100][448] -> WT[448][104] (transposed, zero-padded)
// ---------------------------------------------------------------------------
__global__ void prep_w_kernel(const float* __restrict__ W) {
    int i = blockIdx.x * blockDim.x + threadIdx.x;
    if (i < CC * DPAD) {
        int c = i / DPAD, d = i - c * DPAD;
        g_WT[i] = (d < DP) ? W[d * CC + c] : 0.f;
    }
}

// ---------------------------------------------------------------------------
// prep_mean: tiled transpose mean [100][4096] -> meanT [4096][100]
// grid (128, 4), block (32, 8)
// ---------------------------------------------------------------------------
__global__ void prep_mean_kernel(const float* __restrict__ mean) {
    __shared__ float t[32][33];
    const int n0 = blockIdx.x * 32, c0 = blockIdx.y * 32;
    const int tx = threadIdx.x, ty = threadIdx.y;
#pragma unroll
    for (int j = 0; j < 32; j += 8) {
        int c = c0 + ty + j;
        if (c < DP) t[ty + j][tx] = mean[(size_t)c * NPOS + n0 + tx];
    }
    __syncthreads();
    int c = c0 + tx;
    if (c < DP) {
#pragma unroll
        for (int j = 0; j < 32; j += 8) {
            int n = n0 + ty + j;
            g_meanT[(size_t)n * DP + c] = t[tx][ty + j];
        }
    }
}

// ---------------------------------------------------------------------------
// Projection at 32x32: proj[b][p][d] = sum_c X[b][c][p] * W[d][c] + bias[d]
// Block: 416 threads = 13 warps. warp w -> d0 = 8w (13*8 = 104, zero waste);
// lane l -> p = {2l, 2l+1} of a 64-p tile. W pairs loaded natively as u64
// from g_WT (uniform per warp -> broadcast). X via cp.async double buffer.
// ---------------------------------------------------------------------------
__global__ __launch_bounds__(416) void proj_kernel(const float* __restrict__ X,
                                                   const float* __restrict__ bias) {
    __shared__ float Xs[2][32][64];
    const int tid = threadIdx.x;
    const int lane = tid & 31, dg = tid >> 5;   // dg 0..12
    const int ptile = blockIdx.x;               // 0..15
    const int b = blockIdx.y;                   // 0..31
    const int p2 = lane * 2;
    const int d0 = dg * 8;

    const float* Xb = X + (size_t)b * CC * PIN + ptile * 64;
    unsigned int sbase = (unsigned int)__cvta_generic_to_shared(&Xs[0][0][0]);

    // prologue: load chunk 0 into buf 0
    for (int i = tid; i < 512; i += 416) {
        int c = i >> 4, p4 = (i & 15) * 4;
        cpa16(sbase + (unsigned)((c * 64 + p4) * 4),
              Xb + (size_t)c * PIN + p4);
    }
    asm volatile("cp.async.commit_group;\n");

    unsigned long long acc[8];
#pragma unroll
    for (int k = 0; k < 8; k++) acc[k] = 0ull;

    int buf = 0;
    for (int chunk = 0; chunk < 14; chunk++) {
        const int c0 = chunk * 32;
        asm volatile("cp.async.wait_group 0;\n");
        __syncthreads();
        if (chunk < 13) {
            const float* src = Xb + (size_t)(c0 + 32) * PIN;
            unsigned int dst = sbase + (unsigned)((buf ^ 1) * 2048 * 4);
            for (int i = tid; i < 512; i += 416) {
                int c = i >> 4, p4 = (i & 15) * 4;
                cpa16(dst + (unsigned)((c * 64 + p4) * 4),
                      src + (size_t)c * PIN + p4);
            }
            asm volatile("cp.async.commit_group;\n");
        }
        const float(*Xc)[64] = Xs[buf];
#pragma unroll 8
        for (int c = 0; c < 32; c++) {
            float2 xv = *(const float2*)&Xc[c][p2];
            unsigned long long xd0 = pack2(xv.x, xv.x);
            unsigned long long xd1 = pack2(xv.y, xv.y);
            const ulonglong2* wr =
                (const ulonglong2*)(g_WT + (size_t)(c0 + c) * DPAD + d0);
            ulonglong2 w0 = wr[0];
            ulonglong2 w1 = wr[1];
            acc[0] = fma2(xd0, w0.x, acc[0]);
            acc[1] = fma2(xd0, w0.y, acc[1]);
            acc[2] = fma2(xd0, w1.x, acc[2]);
            acc[3] = fma2(xd0, w1.y, acc[3]);
            acc[4] = fma2(xd1, w0.x, acc[4]);
            acc[5] = fma2(xd1, w0.y, acc[5]);
            acc[6] = fma2(xd1, w1.x, acc[6]);
            acc[7] = fma2(xd1, w1.y, acc[7]);
        }
        buf ^= 1;
    }

    // epilogue
    float4 bi0 = *(const float4*)&bias[d0];
    float4 bi1 = make_float4(0.f, 0.f, 0.f, 0.f);
    if (dg < 12) bi1 = *(const float4*)&bias[d0 + 4];
    const int pg = ptile * 64 + p2;
#pragma unroll
    for (int p = 0; p < 2; p++) {
        float2 u0 = unpack2(acc[p * 4 + 0]);
        float2 u1 = unpack2(acc[p * 4 + 1]);
        float2 u2 = unpack2(acc[p * 4 + 2]);
        float2 u3 = unpack2(acc[p * 4 + 3]);
        float* o = g_proj + ((size_t)b * PIN + pg + p) * DP + d0;
        *(float4*)o = make_float4(u0.x + bi0.x, u0.y + bi0.y,
                                  u1.x + bi0.z, u1.y + bi0.w);
        if (dg < 12)
            *(float4*)(o + 4) = make_float4(u2.x + bi1.x, u2.y + bi1.y,
                                            u3.x + bi1.z, u3.y + bi1.w);
    }
}

// ---------------------------------------------------------------------------
// Fused 2x bilinear upsample + mean-subtract + Mahalanobis quadratic form.
// One block per position n (4096 blocks). 160 threads = 5 warps.
// lane -> batch b (32), warp -> 20 d values (5*20 = 100, zero waste).
// IC pairs loaded natively as ulonglong2 (uniform per warp -> broadcast);
// diff scalar from smem + 1 dup pack per c.
// ---------------------------------------------------------------------------
__global__ __launch_bounds__(160) void maha_kernel(const float* __restrict__ ic) {
    __shared__ float DmT[DP][36];   // [c][b], row stride 144B
    __shared__ float part[5][32];
    const int n = blockIdx.x;
    const int tid = threadIdx.x;
    const int b = tid & 31, dg = tid >> 5;   // dg 0..4

    // bilinear source taps (half-pixel centers, clamped)
    const int yo = n >> 6, xo = n & 63;
    float yin = (yo + 0.5f) * 0.5f - 0.5f;
    float xin = (xo + 0.5f) * 0.5f - 0.5f;
    int y0 = (int)floorf(yin), x0 = (int)floorf(xin);
    float fy = yin - (float)y0, fx = xin - (float)x0;
    int y0c = max(y0, 0), y1c = min(y0 + 1, HWI - 1);
    int x0c = max(x0, 0), x1c = min(x0 + 1, HWI - 1);
    float w00 = (1.f - fy) * (1.f - fx), w01 = (1.f - fy) * fx;
    float w10 = fy * (1.f - fx),         w11 = fy * fx;
    int p00 = y0c * HWI + x0c, p01 = y0c * HWI + x1c;
    int p10 = y1c * HWI + x0c, p11 = y1c * HWI + x1c;

    const float* mt = g_meanT + (size_t)n * DP;
    for (int idx = tid; idx < BB * DP; idx += 160) {
        int bb = idx / DP;
        int c = idx - bb * DP;
        const float* P = g_proj + (size_t)bb * PIN * DP;
        float v = w00 * P[p00 * DP + c] + w01 * P[p01 * DP + c]
                + w10 * P[p10 * DP + c] + w11 * P[p11 * DP + c] - mt[c];
        DmT[c][bb] = v;
    }
    __syncthreads();

    const int d0 = dg * 20;
    const float* icn = ic + (size_t)n * (DP * DP) + d0;

    unsigned long long acc[10];
#pragma unroll
    for (int q = 0; q < 10; q++) acc[q] = 0ull;

#pragma unroll 2
    for (int c = 0; c < DP; c++) {
        float dm = DmT[c][b];
        unsigned long long dmd = pack2(dm, dm);
        const ulonglong2* icp = (const ulonglong2*)(icn + (size_t)c * DP);
        ulonglong2 u0 = icp[0];
        ulonglong2 u1 = icp[1];
        ulonglong2 u2 = icp[2];
        ulonglong2 u3 = icp[3];
        ulonglong2 u4 = icp[4];
        acc[0] = fma2(dmd, u0.x, acc[0]);
        acc[1] = fma2(dmd, u0.y, acc[1]);
        acc[2] = fma2(dmd, u1.x, acc[2]);
        acc[3] = fma2(dmd, u1.y, acc[3]);
        acc[4] = fma2(dmd, u2.x, acc[4]);
        acc[5] = fma2(dmd, u2.y, acc[5]);
        acc[6] = fma2(dmd, u3.x, acc[6]);
        acc[7] = fma2(dmd, u3.y, acc[7]);
        acc[8] = fma2(dmd, u4.x, acc[8]);
        acc[9] = fma2(dmd, u4.y, acc[9]);
    }

    unsigned long long s2 = 0ull;
#pragma unroll
    for (int q = 0; q < 10; q++) {
        unsigned long long qd = pack2(DmT[d0 + 2 * q][b], DmT[d0 + 2 * q + 1][b]);
        s2 = fma2(acc[q], qd, s2);
    }
    float2 s = unpack2(s2);
    part[dg][b] = s.x + s.y;
    __syncthreads();
    if (tid < 32) {
        float t = part[0][tid] + part[1][tid] + part[2][tid]
                + part[3][tid] + part[4][tid];
        g_dist[(size_t)tid * NPOS + n] = t;
    }
}

// ---------------------------------------------------------------------------
// Normalize + 4x bilinear upsample 64x64 -> 256x256 (4 outputs/thread)
// ---------------------------------------------------------------------------
__global__ void upsample_kernel(const float* __restrict__ nmin_p,
                                const float* __restrict__ nmax_p,
                                float* __restrict__ out) {
    const int b = blockIdx.y;
    const int i = blockIdx.x * blockDim.x + threadIdx.x;  // 0..16383
    const int yo = i >> 6;              // 0..255
    const int xb = (i & 63) * 4;        // x base, 4 outputs

    float yin = (yo + 0.5f) * 0.25f - 0.5f;
    int y0 = (int)floorf(yin);
    float fy = yin - (float)y0;
    int y0c = max(y0, 0), y1c = min(y0 + 1, HWF - 1);

    const float* dn = g_dist + (size_t)b * NPOS;
    const float* r0 = dn + y0c * HWF;
    const float* r1 = dn + y1c * HWF;
    float nmin = *nmin_p, nmax = *nmax_p;
    float inv = 1.f / (nmax - nmin + 1e-8f);

    float4 res;
    float* resp = (float*)&res;
#pragma unroll
    for (int k = 0; k < 4; k++) {
        int xo = xb + k;
        float xin = (xo + 0.5f) * 0.25f - 0.5f;
        int x0 = (int)floorf(xin);
        float fx = xin - (float)x0;
        int x0c = max(x0, 0), x1c = min(x0 + 1, HWF - 1);
        float v = (1.f - fy) * ((1.f - fx) * r0[x0c] + fx * r0[x1c])
                + fy * ((1.f - fx) * r1[x0c] + fx * r1[x1c]);
        resp[k] = (v - nmin) * inv;
    }
    *(float4*)&out[(size_t)b * (OHW * OHW) + yo * OHW + xb] = res;
}

// ---------------------------------------------------------------------------
extern "C" void kernel_launch(void* const* d_in, const int* in_sizes, int n_in,
                              void* d_out, int out_size) {
    (void)in_sizes; (void)n_in; (void)out_size;
    const float* combined = (const float*)d_in[0];
    const float* proj_w   = (const float*)d_in[1];
    const float* proj_b   = (const float*)d_in[2];
    const float* mean     = (const float*)d_in[3];
    const float* inv_cov  = (const float*)d_in[4];
    const float* nmin     = (const float*)d_in[5];
    const float* nmax     = (const float*)d_in[6];
    float* out = (float*)d_out;

    prep_w_kernel<<<(CC * DPAD + 255) / 256, 256>>>(proj_w);
    prep_mean_kernel<<<dim3(NPOS / 32, 4), dim3(32, 8)>>>(mean);
    proj_kernel<<<dim3(16, BB), 416>>>(combined, proj_b);
    maha_kernel<<<NPOS, 160>>>(inv_cov);
    upsample_kernel<<<dim3(OHW * OHW / (256 * 4), BB), 256>>>(nmin, nmax, out);
}

// round 4
// speedup vs baseline: 1.1966x; 1.1966x over previous
#include <cuda_runtime.h>

#define BB 32
#define CC 448
#define HWI 32
#define PIN 1024       // 32*32
#define HWF 64
#define NPOS 4096
#define DP 100
#define DPAD 104
#define OHW 256

// ---- packed f32x2 helpers (sm_103a) ----
__device__ __forceinline__ unsigned long long pack2(float lo, float hi) {
    unsigned long long r;
    asm("mov.b64 %0, {%1, %2};" : "=l"(r) : "f"(lo), "f"(hi));
    return r;
}
__device__ __forceinline__ float2 unpack2(unsigned long long v) {
    float lo, hi;
    asm("mov.b64 {%0, %1}, %2;" : "=f"(lo), "=f"(hi) : "l"(v));
    return make_float2(lo, hi);
}
__device__ __forceinline__ unsigned long long fma2(unsigned long long a,
                                                   unsigned long long b,
                                                   unsigned long long c) {
    unsigned long long d;
    asm("fma.rn.f32x2 %0, %1, %2, %3;" : "=l"(d) : "l"(a), "l"(b), "l"(c));
    return d;
}
__device__ __forceinline__ void cpa16(unsigned int saddr, const void* g) {
    asm volatile("cp.async.ca.shared.global [%0], [%1], 16;\n" :: "r"(saddr), "l"(g));
}

// ---- scratch (static device globals; no allocation) ----
__device__ float g_WT[CC * DPAD];          // [c][d], zero-padded d>=100
__device__ float g_meanT[NPOS * DP];       // [n][c]
__device__ float g_proj[(size_t)BB * PIN * DP];  // [b][p][d]  (13.1 MB, fits L2)
__device__ float g_dist[(size_t)BB * NPOS];      // [b][n]

// ---------------------------------------------------------------------------
// prep_w: proj_w [100][448] -> WT[448][104] (transposed, zero-padded)
// ---------------------------------------------------------------------------
__global__ void prep_w_kernel(const float* __restrict__ W) {
    int i = blockIdx.x * blockDim.x + threadIdx.x;
    if (i < CC * DPAD) {
        int c = i / DPAD, d = i - c * DPAD;
        g_WT[i] = (d < DP) ? W[d * CC + c] : 0.f;
    }
}

// ---------------------------------------------------------------------------
// prep_mean: tiled transpose mean [100][4096] -> meanT [4096][100]
// grid (128, 4), block (32, 8)
// ---------------------------------------------------------------------------
__global__ void prep_mean_kernel(const float* __restrict__ mean) {
    __shared__ float t[32][33];
    const int n0 = blockIdx.x * 32, c0 = blockIdx.y * 32;
    const int tx = threadIdx.x, ty = threadIdx.y;
#pragma unroll
    for (int j = 0; j < 32; j += 8) {
        int c = c0 + ty + j;
        if (c < DP) t[ty + j][tx] = mean[(size_t)c * NPOS + n0 + tx];
    }
    __syncthreads();
    int c = c0 + tx;
    if (c < DP) {
#pragma unroll
        for (int j = 0; j < 32; j += 8) {
            int n = n0 + ty + j;
            g_meanT[(size_t)n * DP + c] = t[tx][ty + j];
        }
    }
}

// ---------------------------------------------------------------------------
// Projection at 32x32: proj[b][p][d] = sum_c X[b][c][p] * W[d][c] + bias[d]
// Block: 416 threads = 13 warps. warp -> 8 d (13*8 = 104, zero waste);
// lane -> 2 p of a 64-p tile. W AND X staged in smem via cp.async double
// buffer; W pairs read as native ulonglong2 LDS (broadcast, conflict-free).
// ---------------------------------------------------------------------------
__global__ __launch_bounds__(416) void proj_kernel(const float* __restrict__ X,
                                                   const float* __restrict__ bias) {
    __shared__ float Xs[2][32][64];      // 16 KB
    __shared__ float Ws[2][32][DPAD];    // 26.6 KB
    const int tid = threadIdx.x;
    const int lane = tid & 31, dg = tid >> 5;   // dg 0..12
    const int ptile = blockIdx.x;               // 0..15
    const int b = blockIdx.y;                   // 0..31
    const int p2 = lane * 2;
    const int d0 = dg * 8;

    const float* Xb = X + (size_t)b * CC * PIN + ptile * 64;
    unsigned int xbase = (unsigned int)__cvta_generic_to_shared(&Xs[0][0][0]);
    unsigned int wbase = (unsigned int)__cvta_generic_to_shared(&Ws[0][0][0]);

    // prologue: chunk 0 into buf 0
    for (int i = tid; i < 512; i += 416) {
        int c = i >> 4, p4 = (i & 15) * 4;
        cpa16(xbase + (unsigned)((c * 64 + p4) * 4), Xb + (size_t)c * PIN + p4);
    }
    for (int i = tid; i < 832; i += 416) {
        int c = i / 26, d4 = (i - c * 26) * 4;
        cpa16(wbase + (unsigned)((c * DPAD + d4) * 4), g_WT + c * DPAD + d4);
    }
    asm volatile("cp.async.commit_group;\n");

    unsigned long long acc[8];
#pragma unroll
    for (int k = 0; k < 8; k++) acc[k] = 0ull;

    int buf = 0;
    for (int chunk = 0; chunk < 14; chunk++) {
        const int c0 = chunk * 32;
        asm volatile("cp.async.wait_group 0;\n");
        __syncthreads();
        if (chunk < 13) {
            const float* xsrc = Xb + (size_t)(c0 + 32) * PIN;
            const float* wsrc = g_WT + (c0 + 32) * DPAD;
            unsigned int xdst = xbase + (unsigned)((buf ^ 1) * 2048 * 4);
            unsigned int wdst = wbase + (unsigned)((buf ^ 1) * 32 * DPAD * 4);
            for (int i = tid; i < 512; i += 416) {
                int c = i >> 4, p4 = (i & 15) * 4;
                cpa16(xdst + (unsigned)((c * 64 + p4) * 4),
                      xsrc + (size_t)c * PIN + p4);
            }
            for (int i = tid; i < 832; i += 416) {
                int c = i / 26, d4 = (i - c * 26) * 4;
                cpa16(wdst + (unsigned)((c * DPAD + d4) * 4),
                      wsrc + c * DPAD + d4);
            }
            asm volatile("cp.async.commit_group;\n");
        }
        const float(*Xc)[64] = Xs[buf];
        const float(*Wc)[DPAD] = Ws[buf];
#pragma unroll 8
        for (int c = 0; c < 32; c++) {
            float2 xv = *(const float2*)&Xc[c][p2];
            unsigned long long xd0 = pack2(xv.x, xv.x);
            unsigned long long xd1 = pack2(xv.y, xv.y);
            ulonglong2 w0 = *(const ulonglong2*)&Wc[c][d0];
            ulonglong2 w1 = *(const ulonglong2*)&Wc[c][d0 + 4];
            acc[0] = fma2(xd0, w0.x, acc[0]);
            acc[1] = fma2(xd0, w0.y, acc[1]);
            acc[2] = fma2(xd0, w1.x, acc[2]);
            acc[3] = fma2(xd0, w1.y, acc[3]);
            acc[4] = fma2(xd1, w0.x, acc[4]);
            acc[5] = fma2(xd1, w0.y, acc[5]);
            acc[6] = fma2(xd1, w1.x, acc[6]);
            acc[7] = fma2(xd1, w1.y, acc[7]);
        }
        buf ^= 1;
    }

    // epilogue
    float4 bi0 = *(const float4*)&bias[d0];
    float4 bi1 = make_float4(0.f, 0.f, 0.f, 0.f);
    if (dg < 12) bi1 = *(const float4*)&bias[d0 + 4];
    const int pg = ptile * 64 + p2;
#pragma unroll
    for (int p = 0; p < 2; p++) {
        float2 u0 = unpack2(acc[p * 4 + 0]);
        float2 u1 = unpack2(acc[p * 4 + 1]);
        float2 u2 = unpack2(acc[p * 4 + 2]);
        float2 u3 = unpack2(acc[p * 4 + 3]);
        float* o = g_proj + ((size_t)b * PIN + pg + p) * DP + d0;
        *(float4*)o = make_float4(u0.x + bi0.x, u0.y + bi0.y,
                                  u1.x + bi0.z, u1.y + bi0.w);
        if (dg < 12)
            *(float4*)(o + 4) = make_float4(u2.x + bi1.x, u2.y + bi1.y,
                                            u3.x + bi1.z, u3.y + bi1.w);
    }
}

// ---------------------------------------------------------------------------
// Fused 2x bilinear upsample + mean-subtract + Mahalanobis quadratic form.
// One block per position n (4096 blocks). 128 threads.
// Phase 1: DmT[c][b] in smem (bilinear taps from g_proj, L2-resident).
// Phase 2: thread (bg=(t&3)*8, d0=(t>>2)*4), t<100: one distributed LDG.128
// of IC per warp-c (coalesced 128B/warp), b-pairs native from smem.
// ---------------------------------------------------------------------------
__global__ __launch_bounds__(128) void maha_kernel(const float* __restrict__ ic) {
    __shared__ float DmT[DP][36];   // [c][b], row stride 144B
    __shared__ float dists[BB];
    const int n = blockIdx.x;
    const int tid = threadIdx.x;

    // bilinear source taps (half-pixel centers, clamped)
    const int yo = n >> 6, xo = n & 63;
    float yin = (yo + 0.5f) * 0.5f - 0.5f;
    float xin = (xo + 0.5f) * 0.5f - 0.5f;
    int y0 = (int)floorf(yin), x0 = (int)floorf(xin);
    float fy = yin - (float)y0, fx = xin - (float)x0;
    int y0c = max(y0, 0), y1c = min(y0 + 1, HWI - 1);
    int x0c = max(x0, 0), x1c = min(x0 + 1, HWI - 1);
    float w00 = (1.f - fy) * (1.f - fx), w01 = (1.f - fy) * fx;
    float w10 = fy * (1.f - fx),         w11 = fy * fx;
    int p00 = y0c * HWI + x0c, p01 = y0c * HWI + x1c;
    int p10 = y1c * HWI + x0c, p11 = y1c * HWI + x1c;

    const float* mt = g_meanT + (size_t)n * DP;
    for (int idx = tid; idx < BB * DP; idx += 128) {
        int b = idx / DP;
        int c = idx - b * DP;
        const float* P = g_proj + (size_t)b * PIN * DP;
        float v = w00 * P[p00 * DP + c] + w01 * P[p01 * DP + c]
                + w10 * P[p10 * DP + c] + w11 * P[p11 * DP + c] - mt[c];
        DmT[c][b] = v;
    }
    if (tid < BB) dists[tid] = 0.f;
    __syncthreads();

    if (tid < 100) {
        const int bg = (tid & 3) * 8;        // batch base (0,8,16,24)
        const int d0 = (tid >> 2) * 4;       // d base (0..96)
        const float* icn = ic + (size_t)n * (DP * DP) + d0;

        unsigned long long acc[4][4];        // [b-pair j][d-component q]
#pragma unroll
        for (int j = 0; j < 4; j++)
#pragma unroll
            for (int q = 0; q < 4; q++) acc[j][q] = 0ull;

#pragma unroll 4
        for (int c = 0; c < DP; c++) {
            float4 icv = __ldg(reinterpret_cast<const float4*>(icn + c * DP));
            unsigned long long icd[4];
            icd[0] = pack2(icv.x, icv.x);
            icd[1] = pack2(icv.y, icv.y);
            icd[2] = pack2(icv.z, icv.z);
            icd[3] = pack2(icv.w, icv.w);
            ulonglong2 da = *(const ulonglong2*)&DmT[c][bg];
            ulonglong2 db = *(const ulonglong2*)&DmT[c][bg + 4];
            unsigned long long dm[4] = {da.x, da.y, db.x, db.y};
#pragma unroll
            for (int j = 0; j < 4; j++)
#pragma unroll
                for (int q = 0; q < 4; q++)
                    acc[j][q] = fma2(dm[j], icd[q], acc[j][q]);
        }
#pragma unroll
        for (int j = 0; j < 4; j++) {
            unsigned long long s2 = 0ull;
#pragma unroll
            for (int q = 0; q < 4; q++) {
                unsigned long long dp =
                    *(const unsigned long long*)&DmT[d0 + q][bg + 2 * j];
                s2 = fma2(acc[j][q], dp, s2);
            }
            float2 s = unpack2(s2);
            atomicAdd(&dists[bg + 2 * j], s.x);
            atomicAdd(&dists[bg + 2 * j + 1], s.y);
        }
    }
    __syncthreads();
    if (tid < BB) g_dist[(size_t)tid * NPOS + n] = dists[tid];
}

// ---------------------------------------------------------------------------
// Normalize + 4x bilinear upsample 64x64 -> 256x256 (4 outputs/thread)
// ---------------------------------------------------------------------------
__global__ void upsample_kernel(const float* __restrict__ nmin_p,
                                const float* __restrict__ nmax_p,
                                float* __restrict__ out) {
    const int b = blockIdx.y;
    const int i = blockIdx.x * blockDim.x + threadIdx.x;  // 0..16383
    const int yo = i >> 6;              // 0..255
    const int xb = (i & 63) * 4;        // x base, 4 outputs

    float yin = (yo + 0.5f) * 0.25f - 0.5f;
    int y0 = (int)floorf(yin);
    float fy = yin - (float)y0;
    int y0c = max(y0, 0), y1c = min(y0 + 1, HWF - 1);

    const float* dn = g_dist + (size_t)b * NPOS;
    const float* r0 = dn + y0c * HWF;
    const float* r1 = dn + y1c * HWF;
    float nmin = *nmin_p, nmax = *nmax_p;
    float inv = 1.f / (nmax - nmin + 1e-8f);

    float4 res;
    float* resp = (float*)&res;
#pragma unroll
    for (int k = 0; k < 4; k++) {
        int xo = xb + k;
        float xin = (xo + 0.5f) * 0.25f - 0.5f;
        int x0 = (int)floorf(xin);
        float fx = xin - (float)x0;
        int x0c = max(x0, 0), x1c = min(x0 + 1, HWF - 1);
        float v = (1.f - fy) * ((1.f - fx) * r0[x0c] + fx * r0[x1c])
                + fy * ((1.f - fx) * r1[x0c] + fx * r1[x1c]);
        resp[k] = (v - nmin) * inv;
    }
    *(float4*)&out[(size_t)b * (OHW * OHW) + yo * OHW + xb] = res;
}

// ---------------------------------------------------------------------------
extern "C" void kernel_launch(void* const* d_in, const int* in_sizes, int n_in,
                              void* d_out, int out_size) {
    (void)in_sizes; (void)n_in; (void)out_size;
    const float* combined = (const float*)d_in[0];
    const float* proj_w   = (const float*)d_in[1];
    const float* proj_b   = (const float*)d_in[2];
    const float* mean     = (const float*)d_in[3];
    const float* inv_cov  = (const float*)d_in[4];
    const float* nmin     = (const float*)d_in[5];
    const float* nmax     = (const float*)d_in[6];
    float* out = (float*)d_out;

    prep_w_kernel<<<(CC * DPAD + 255) / 256, 256>>>(proj_w);
    prep_mean_kernel<<<dim3(NPOS / 32, 4), dim3(32, 8)>>>(mean);
    proj_kernel<<<dim3(16, BB), 416>>>(combined, proj_b);
    maha_kernel<<<NPOS, 128>>>(inv_cov);
    upsample_kernel<<<dim3(OHW * OHW / (256 * 4), BB), 256>>>(nmin, nmax, out);
}

// round 5
// speedup vs baseline: 1.8356x; 1.5340x over previous
#include <cuda_runtime.h>

#define BB 32
#define CC 448
#define HWI 32
#define PIN 1024       // 32*32
#define HWF 64
#define NPOS 4096
#define DP 100
#define DPAD 104
#define OHW 256
#define CCHUNK 20      // c per IC chunk
#define NCHUNK 5

// ---- packed f32x2 helpers (sm_103a) ----
__device__ __forceinline__ unsigned long long pack2(float lo, float hi) {
    unsigned long long r;
    asm("mov.b64 %0, {%1, %2};" : "=l"(r) : "f"(lo), "f"(hi));
    return r;
}
__device__ __forceinline__ float2 unpack2(unsigned long long v) {
    float lo, hi;
    asm("mov.b64 {%0, %1}, %2;" : "=f"(lo), "=f"(hi) : "l"(v));
    return make_float2(lo, hi);
}
__device__ __forceinline__ unsigned long long fma2(unsigned long long a,
                                                   unsigned long long b,
                                                   unsigned long long c) {
    unsigned long long d;
    asm("fma.rn.f32x2 %0, %1, %2, %3;" : "=l"(d) : "l"(a), "l"(b), "l"(c));
    return d;
}
__device__ __forceinline__ void mbar_init(unsigned int mbar, unsigned int cnt) {
    asm volatile("mbarrier.init.shared.b64 [%0], %1;" :: "r"(mbar), "r"(cnt) : "memory");
}
__device__ __forceinline__ void mbar_expect_tx(unsigned int mbar, unsigned int bytes) {
    asm volatile("mbarrier.arrive.expect_tx.shared.b64 _, [%0], %1;"
                 :: "r"(mbar), "r"(bytes) : "memory");
}
__device__ __forceinline__ void bulk_g2s(unsigned int sdst, const void* gsrc,
                                         unsigned int bytes, unsigned int mbar) {
    asm volatile("cp.async.bulk.shared::cta.global.mbarrier::complete_tx::bytes "
                 "[%0], [%1], %2, [%3];"
                 :: "r"(sdst), "l"(gsrc), "r"(bytes), "r"(mbar) : "memory");
}
__device__ __forceinline__ void mbar_wait(unsigned int mbar, unsigned int parity) {
    asm volatile(
        "{\n\t.reg .pred P;\n\t"
        "WAIT_%=:\n\t"
        "mbarrier.try_wait.parity.acquire.cta.shared::cta.b64 P, [%0], %1, 0x989680;\n\t"
        "@P bra.uni DONE_%=;\n\t"
        "bra.uni WAIT_%=;\n\t"
        "DONE_%=:\n\t}"
        :: "r"(mbar), "r"(parity) : "memory");
}

// ---- scratch (static device globals; no allocation) ----
__device__ float g_WT[CC * DPAD];          // [c][d], zero-padded d>=100
__device__ float g_meanT[NPOS * DP];       // [n][c]
__device__ float g_proj[(size_t)BB * PIN * DP];  // [b][p][d]  (13.1 MB, fits L2)
__device__ float g_dist[(size_t)BB * NPOS];      // [b][n]

// ---------------------------------------------------------------------------
// prep_w: proj_w [100][448] -> WT[448][104] (transposed, zero-padded)
// ---------------------------------------------------------------------------
__global__ void prep_w_kernel(const float* __restrict__ W) {
    int i = blockIdx.x * blockDim.x + threadIdx.x;
    if (i < CC * DPAD) {
        int c = i / DPAD, d = i - c * DPAD;
        g_WT[i] = (d < DP) ? W[d * CC + c] : 0.f;
    }
}

// ---------------------------------------------------------------------------
// prep_mean: tiled transpose mean [100][4096] -> meanT [4096][100]
// ---------------------------------------------------------------------------
__global__ void prep_mean_kernel(const float* __restrict__ mean) {
    __shared__ float t[32][33];
    const int n0 = blockIdx.x * 32, c0 = blockIdx.y * 32;
    const int tx = threadIdx.x, ty = threadIdx.y;
#pragma unroll
    for (int j = 0; j < 32; j += 8) {
        int c = c0 + ty + j;
        if (c < DP) t[ty + j][tx] = mean[(size_t)c * NPOS + n0 + tx];
    }
    __syncthreads();
    int c = c0 + tx;
    if (c < DP) {
#pragma unroll
        for (int j = 0; j < 32; j += 8) {
            int n = n0 + ty + j;
            g_meanT[(size_t)n * DP + c] = t[tx][ty + j];
        }
    }
}

// ---------------------------------------------------------------------------
// Projection at 32x32 (R2-proven version, ~FFMA2 floor).
// Tile: 64 p x 104 d per block, thread = 8p x 8d (f32x2 pairs along d).
// ---------------------------------------------------------------------------
__global__ __launch_bounds__(104) void proj_kernel(const float* __restrict__ X,
                                                   const float* __restrict__ bias) {
    __shared__ float Xs[32][64];     // [c][p]
    __shared__ float Ws[32][DPAD];   // [c][d]
    const int tid = threadIdx.x;
    const int ptile = blockIdx.x;    // 0..15
    const int b = blockIdx.y;        // 0..31
    const int pg = tid & 7;
    const int dg = tid >> 3;         // 0..12
    const int d0 = dg * 8;

    unsigned long long acc[8][4];
#pragma unroll
    for (int k = 0; k < 8; k++)
#pragma unroll
        for (int q = 0; q < 4; q++) acc[k][q] = 0ull;

    const float* Xb = X + ((size_t)b * CC) * PIN + ptile * 64;

    for (int c0 = 0; c0 < CC; c0 += 32) {
        for (int i = tid; i < 32 * 64; i += 104) {
            int c = i >> 6, p = i & 63;
            Xs[c][p] = Xb[(size_t)(c0 + c) * PIN + p];
        }
#pragma unroll
        for (int k = 0; k < 32; k++)
            Ws[k][tid] = g_WT[(c0 + k) * DPAD + tid];
        __syncthreads();

#pragma unroll 4
        for (int c = 0; c < 32; c++) {
            float4 x0 = *(const float4*)&Xs[c][pg * 8];
            float4 x1 = *(const float4*)&Xs[c][pg * 8 + 4];
            ulonglong2 wa = *(const ulonglong2*)&Ws[c][d0];
            ulonglong2 wb = *(const ulonglong2*)&Ws[c][d0 + 4];
            unsigned long long wp[4] = {wa.x, wa.y, wb.x, wb.y};
            float xv[8] = {x0.x, x0.y, x0.z, x0.w, x1.x, x1.y, x1.z, x1.w};
            unsigned long long xd[8];
#pragma unroll
            for (int k = 0; k < 8; k++) xd[k] = pack2(xv[k], xv[k]);
#pragma unroll
            for (int k = 0; k < 8; k++)
#pragma unroll
                for (int q = 0; q < 4; q++)
                    acc[k][q] = fma2(xd[k], wp[q], acc[k][q]);
        }
        __syncthreads();
    }

    float4 bi0 = *(const float4*)&bias[d0];
    float4 bi1 = make_float4(0.f, 0.f, 0.f, 0.f);
    if (dg < 12) bi1 = *(const float4*)&bias[d0 + 4];
    const int pbase = ptile * 64 + pg * 8;
#pragma unroll
    for (int k = 0; k < 8; k++) {
        float* o = g_proj + ((size_t)b * PIN + pbase + k) * DP + d0;
        float2 u0 = unpack2(acc[k][0]);
        float2 u1 = unpack2(acc[k][1]);
        *(float4*)o = make_float4(u0.x + bi0.x, u0.y + bi0.y,
                                  u1.x + bi0.z, u1.y + bi0.w);
        if (dg < 12) {
            float2 u2 = unpack2(acc[k][2]);
            float2 u3 = unpack2(acc[k][3]);
            *(float4*)(o + 4) = make_float4(u2.x + bi1.x, u2.y + bi1.y,
                                            u3.x + bi1.z, u3.y + bi1.w);
        }
    }
}

// ---------------------------------------------------------------------------
// Fused 2x bilinear upsample + mean-subtract + Mahalanobis quadratic form.
// One block per n. 128 threads. IC staged via cp.async.bulk (TMA) double
// buffer (5 chunks x 20 c x 400B); compute reads IC via broadcast LDS.
// ---------------------------------------------------------------------------
__global__ __launch_bounds__(128) void maha_kernel(const float* __restrict__ ic) {
    __shared__ float DmT[DP][36];                // [c][b]
    __shared__ float ICs[2][CCHUNK * DP];        // 2 x 8000B
    __shared__ float dists[BB];
    __shared__ __align__(8) unsigned long long mbar_sto[2];
    const int n = blockIdx.x;
    const int tid = threadIdx.x;

    unsigned int mbar0 = (unsigned int)__cvta_generic_to_shared(&mbar_sto[0]);
    unsigned int mbar1 = (unsigned int)__cvta_generic_to_shared(&mbar_sto[1]);
    unsigned int ics0 = (unsigned int)__cvta_generic_to_shared(&ICs[0][0]);
    unsigned int ics1 = (unsigned int)__cvta_generic_to_shared(&ICs[1][0]);
    const float* icn = ic + (size_t)n * (DP * DP);

    if (tid == 0) {
        mbar_init(mbar0, 1);
        mbar_init(mbar1, 1);
        asm volatile("fence.proxy.async.shared::cta;" ::: "memory");
        mbar_expect_tx(mbar0, CCHUNK * DP * 4);
        bulk_g2s(ics0, icn, CCHUNK * DP * 4, mbar0);
    }

    // bilinear source taps (half-pixel centers, clamped)
    const int yo = n >> 6, xo = n & 63;
    float yin = (yo + 0.5f) * 0.5f - 0.5f;
    float xin = (xo + 0.5f) * 0.5f - 0.5f;
    int y0 = (int)floorf(yin), x0 = (int)floorf(xin);
    float fy = yin - (float)y0, fx = xin - (float)x0;
    int y0c = max(y0, 0), y1c = min(y0 + 1, HWI - 1);
    int x0c = max(x0, 0), x1c = min(x0 + 1, HWI - 1);
    float w00 = (1.f - fy) * (1.f - fx), w01 = (1.f - fy) * fx;
    float w10 = fy * (1.f - fx),         w11 = fy * fx;
    int p00 = y0c * HWI + x0c, p01 = y0c * HWI + x1c;
    int p10 = y1c * HWI + x0c, p11 = y1c * HWI + x1c;

    // phase 1: DmT[c][b] via float4 taps (25 c-quads x 32 b)
    const float* mt = g_meanT + (size_t)n * DP;
#pragma unroll 2
    for (int idx = tid; idx < 800; idx += 128) {
        int b = idx / 25;
        int q = idx - b * 25;
        int c = q * 4;
        const float* P = g_proj + (size_t)b * PIN * DP;
        float4 t00 = *(const float4*)&P[p00 * DP + c];
        float4 t01 = *(const float4*)&P[p01 * DP + c];
        float4 t10 = *(const float4*)&P[p10 * DP + c];
        float4 t11 = *(const float4*)&P[p11 * DP + c];
        float4 m4 = *(const float4*)&mt[c];
        DmT[c + 0][b] = w00 * t00.x + w01 * t01.x + w10 * t10.x + w11 * t11.x - m4.x;
        DmT[c + 1][b] = w00 * t00.y + w01 * t01.y + w10 * t10.y + w11 * t11.y - m4.y;
        DmT[c + 2][b] = w00 * t00.z + w01 * t01.z + w10 * t10.z + w11 * t11.z - m4.z;
        DmT[c + 3][b] = w00 * t00.w + w01 * t01.w + w10 * t10.w + w11 * t11.w - m4.w;
    }
    if (tid < BB) dists[tid] = 0.f;
    __syncthreads();

    const int bg = (tid & 3) * 8;        // batch base
    const int d0 = (tid >> 2) * 4;       // d base

    unsigned long long acc[4][4];
#pragma unroll
    for (int j = 0; j < 4; j++)
#pragma unroll
        for (int q = 0; q < 4; q++) acc[j][q] = 0ull;

    for (int k = 0; k < NCHUNK; k++) {
        if (tid == 0 && k + 1 < NCHUNK) {
            unsigned int dst = (k + 1) & 1 ? ics1 : ics0;
            unsigned int mb = (k + 1) & 1 ? mbar1 : mbar0;
            mbar_expect_tx(mb, CCHUNK * DP * 4);
            bulk_g2s(dst, icn + (k + 1) * CCHUNK * DP, CCHUNK * DP * 4, mb);
        }
        mbar_wait(k & 1 ? mbar1 : mbar0, (k >> 1) & 1);
        if (tid < 100) {
            const float* icc = &ICs[k & 1][0] + d0;
#pragma unroll 4
            for (int cc = 0; cc < CCHUNK; cc++) {
                float4 icv = *(const float4*)(icc + cc * DP);
                unsigned long long icd[4];
                icd[0] = pack2(icv.x, icv.x);
                icd[1] = pack2(icv.y, icv.y);
                icd[2] = pack2(icv.z, icv.z);
                icd[3] = pack2(icv.w, icv.w);
                int c = k * CCHUNK + cc;
                ulonglong2 da = *(const ulonglong2*)&DmT[c][bg];
                ulonglong2 db = *(const ulonglong2*)&DmT[c][bg + 4];
                unsigned long long dm[4] = {da.x, da.y, db.x, db.y};
#pragma unroll
                for (int j = 0; j < 4; j++)
#pragma unroll
                    for (int q = 0; q < 4; q++)
                        acc[j][q] = fma2(dm[j], icd[q], acc[j][q]);
            }
        }
        __syncthreads();
    }

    if (tid < 100) {
#pragma unroll
        for (int j = 0; j < 4; j++) {
            unsigned long long s2 = 0ull;
#pragma unroll
            for (int q = 0; q < 4; q++) {
                unsigned long long dp =
                    *(const unsigned long long*)&DmT[d0 + q][bg + 2 * j];
                s2 = fma2(acc[j][q], dp, s2);
            }
            float2 s = unpack2(s2);
            atomicAdd(&dists[bg + 2 * j], s.x);
            atomicAdd(&dists[bg + 2 * j + 1], s.y);
        }
    }
    __syncthreads();
    if (tid < BB) g_dist[(size_t)tid * NPOS + n] = dists[tid];
}

// ---------------------------------------------------------------------------
// Normalize + 4x bilinear upsample 64x64 -> 256x256 (4 outputs/thread)
// ---------------------------------------------------------------------------
__global__ void upsample_kernel(const float* __restrict__ nmin_p,
                                const float* __restrict__ nmax_p,
                                float* __restrict__ out) {
    const int b = blockIdx.y;
    const int i = blockIdx.x * blockDim.x + threadIdx.x;
    const int yo = i >> 6;
    const int xb = (i & 63) * 4;

    float yin = (yo + 0.5f) * 0.25f - 0.5f;
    int y0 = (int)floorf(yin);
    float fy = yin - (float)y0;
    int y0c = max(y0, 0), y1c = min(y0 + 1, HWF - 1);

    const float* dn = g_dist + (size_t)b * NPOS;
    const float* r0 = dn + y0c * HWF;
    const float* r1 = dn + y1c * HWF;
    float nmin = *nmin_p, nmax = *nmax_p;
    float inv = 1.f / (nmax - nmin + 1e-8f);

    float4 res;
    float* resp = (float*)&res;
#pragma unroll
    for (int k = 0; k < 4; k++) {
        int xo = xb + k;
        float xin = (xo + 0.5f) * 0.25f - 0.5f;
        int x0 = (int)floorf(xin);
        float fx = xin - (float)x0;
        int x0c = max(x0, 0), x1c = min(x0 + 1, HWF - 1);
        float v = (1.f - fy) * ((1.f - fx) * r0[x0c] + fx * r0[x1c])
                + fy * ((1.f - fx) * r1[x0c] + fx * r1[x1c]);
        resp[k] = (v - nmin) * inv;
    }
    *(float4*)&out[(size_t)b * (OHW * OHW) + yo * OHW + xb] = res;
}

// ---------------------------------------------------------------------------
extern "C" void kernel_launch(void* const* d_in, const int* in_sizes, int n_in,
                              void* d_out, int out_size) {
    (void)in_sizes; (void)n_in; (void)out_size;
    const float* combined = (const float*)d_in[0];
    const float* proj_w   = (const float*)d_in[1];
    const float* proj_b   = (const float*)d_in[2];
    const float* mean     = (const float*)d_in[3];
    const float* inv_cov  = (const float*)d_in[4];
    const float* nmin     = (const float*)d_in[5];
    const float* nmax     = (const float*)d_in[6];
    float* out = (float*)d_out;

    prep_w_kernel<<<(CC * DPAD + 255) / 256, 256>>>(proj_w);
    prep_mean_kernel<<<dim3(NPOS / 32, 4), dim3(32, 8)>>>(mean);
    proj_kernel<<<dim3(16, BB), 104>>>(combined, proj_b);
    maha_kernel<<<NPOS, 128>>>(inv_cov);
    upsample_kernel<<<dim3(OHW * OHW / (256 * 4), BB), 256>>>(nmin, nmax, out);
}

// round 6
// speedup vs baseline: 1.8429x; 1.0040x over previous
#include <cuda_runtime.h>

#define BB 32
#define CC 448
#define HWI 32
#define PIN 1024       // 32*32
#define HWF 64
#define NPOS 4096
#define DP 100
#define DPAD 104
#define OHW 256
#define CCHUNK 20      // c per IC chunk
#define NCHUNK 5

// ---- packed f32x2 helpers (sm_103a) ----
__device__ __forceinline__ unsigned long long pack2(float lo, float hi) {
    unsigned long long r;
    asm("mov.b64 %0, {%1, %2};" : "=l"(r) : "f"(lo), "f"(hi));
    return r;
}
__device__ __forceinline__ float2 unpack2(unsigned long long v) {
    float lo, hi;
    asm("mov.b64 {%0, %1}, %2;" : "=f"(lo), "=f"(hi) : "l"(v));
    return make_float2(lo, hi);
}
__device__ __forceinline__ unsigned long long fma2(unsigned long long a,
                                                   unsigned long long b,
                                                   unsigned long long c) {
    unsigned long long d;
    asm("fma.rn.f32x2 %0, %1, %2, %3;" : "=l"(d) : "l"(a), "l"(b), "l"(c));
    return d;
}
__device__ __forceinline__ void mbar_init(unsigned int mbar, unsigned int cnt) {
    asm volatile("mbarrier.init.shared.b64 [%0], %1;" :: "r"(mbar), "r"(cnt) : "memory");
}
__device__ __forceinline__ void mbar_expect_tx(unsigned int mbar, unsigned int bytes) {
    asm volatile("mbarrier.arrive.expect_tx.shared.b64 _, [%0], %1;"
                 :: "r"(mbar), "r"(bytes) : "memory");
}
__device__ __forceinline__ void bulk_g2s(unsigned int sdst, const void* gsrc,
                                         unsigned int bytes, unsigned int mbar) {
    asm volatile("cp.async.bulk.shared::cta.global.mbarrier::complete_tx::bytes "
                 "[%0], [%1], %2, [%3];"
                 :: "r"(sdst), "l"(gsrc), "r"(bytes), "r"(mbar) : "memory");
}
__device__ __forceinline__ void mbar_wait(unsigned int mbar, unsigned int parity) {
    asm volatile(
        "{\n\t.reg .pred P;\n\t"
        "WAIT_%=:\n\t"
        "mbarrier.try_wait.parity.acquire.cta.shared::cta.b64 P, [%0], %1, 0x989680;\n\t"
        "@P bra.uni DONE_%=;\n\t"
        "bra.uni WAIT_%=;\n\t"
        "DONE_%=:\n\t}"
        :: "r"(mbar), "r"(parity) : "memory");
}

// ---- scratch (static device globals; no allocation) ----
__device__ float g_WT[CC * DPAD];          // [c][d], zero-padded d>=100
__device__ float g_meanT[NPOS * DP];       // [n][c]
__device__ float g_proj[(size_t)BB * PIN * DP];  // [b][p][d]  (13.1 MB, fits L2)
__device__ float g_dist[(size_t)BB * NPOS];      // [b][n]

// ---------------------------------------------------------------------------
// prep_w: proj_w [100][448] -> WT[448][104] (transposed, zero-padded)
// ---------------------------------------------------------------------------
__global__ void prep_w_kernel(const float* __restrict__ W) {
    int i = blockIdx.x * blockDim.x + threadIdx.x;
    if (i < CC * DPAD) {
        int c = i / DPAD, d = i - c * DPAD;
        g_WT[i] = (d < DP) ? W[d * CC + c] : 0.f;
    }
}

// ---------------------------------------------------------------------------
// prep_mean: tiled transpose mean [100][4096] -> meanT [4096][100]
// ---------------------------------------------------------------------------
__global__ void prep_mean_kernel(const float* __restrict__ mean) {
    __shared__ float t[32][33];
    const int n0 = blockIdx.x * 32, c0 = blockIdx.y * 32;
    const int tx = threadIdx.x, ty = threadIdx.y;
#pragma unroll
    for (int j = 0; j < 32; j += 8) {
        int c = c0 + ty + j;
        if (c < DP) t[ty + j][tx] = mean[(size_t)c * NPOS + n0 + tx];
    }
    __syncthreads();
    int c = c0 + tx;
    if (c < DP) {
#pragma unroll
        for (int j = 0; j < 32; j += 8) {
            int n = n0 + ty + j;
            g_meanT[(size_t)n * DP + c] = t[tx][ty + j];
        }
    }
}

// ---------------------------------------------------------------------------
// Projection at 32x32: proj[b][p][d] = sum_c X[b][c][p] * W[d][c] + bias[d]
// Block: 208 threads. Thread = 4p x 8d (f32x2 pairs along d).
// pg = tid & 15 (p base pg*4), dg = tid >> 4 (0..12, d base dg*8).
// ---------------------------------------------------------------------------
__global__ __launch_bounds__(208) void proj_kernel(const float* __restrict__ X,
                                                   const float* __restrict__ bias) {
    __shared__ float Xs[32][64];     // [c][p]
    __shared__ float Ws[32][DPAD];   // [c][d]
    const int tid = threadIdx.x;
    const int ptile = blockIdx.x;    // 0..15
    const int b = blockIdx.y;        // 0..31
    const int pg = tid & 15;         // p base = pg*4
    const int dg = tid >> 4;         // 0..12
    const int d0 = dg * 8;

    unsigned long long acc[4][4];
#pragma unroll
    for (int k = 0; k < 4; k++)
#pragma unroll
        for (int q = 0; q < 4; q++) acc[k][q] = 0ull;

    const float* Xb = X + ((size_t)b * CC) * PIN + ptile * 64;

    for (int c0 = 0; c0 < CC; c0 += 32) {
        for (int i = tid; i < 32 * 64; i += 208) {
            int c = i >> 6, p = i & 63;
            Xs[c][p] = Xb[(size_t)(c0 + c) * PIN + p];
        }
        for (int i = tid; i < 32 * DPAD; i += 208) {
            int c = i / DPAD, d = i - c * DPAD;
            Ws[c][d] = g_WT[(c0 + c) * DPAD + d];
        }
        __syncthreads();

#pragma unroll 4
        for (int c = 0; c < 32; c++) {
            float4 x0 = *(const float4*)&Xs[c][pg * 4];
            ulonglong2 wa = *(const ulonglong2*)&Ws[c][d0];
            ulonglong2 wb = *(const ulonglong2*)&Ws[c][d0 + 4];
            unsigned long long wp[4] = {wa.x, wa.y, wb.x, wb.y};
            float xv[4] = {x0.x, x0.y, x0.z, x0.w};
            unsigned long long xd[4];
#pragma unroll
            for (int k = 0; k < 4; k++) xd[k] = pack2(xv[k], xv[k]);
#pragma unroll
            for (int k = 0; k < 4; k++)
#pragma unroll
                for (int q = 0; q < 4; q++)
                    acc[k][q] = fma2(xd[k], wp[q], acc[k][q]);
        }
        __syncthreads();
    }

    float4 bi0 = *(const float4*)&bias[d0];
    float4 bi1 = make_float4(0.f, 0.f, 0.f, 0.f);
    if (dg < 12) bi1 = *(const float4*)&bias[d0 + 4];
    const int pbase = ptile * 64 + pg * 4;
#pragma unroll
    for (int k = 0; k < 4; k++) {
        float* o = g_proj + ((size_t)b * PIN + pbase + k) * DP + d0;
        float2 u0 = unpack2(acc[k][0]);
        float2 u1 = unpack2(acc[k][1]);
        *(float4*)o = make_float4(u0.x + bi0.x, u0.y + bi0.y,
                                  u1.x + bi0.z, u1.y + bi0.w);
        if (dg < 12) {
            float2 u2 = unpack2(acc[k][2]);
            float2 u3 = unpack2(acc[k][3]);
            *(float4*)(o + 4) = make_float4(u2.x + bi1.x, u2.y + bi1.y,
                                            u3.x + bi1.z, u3.y + bi1.w);
        }
    }
}

// ---------------------------------------------------------------------------
// Fused 2x bilinear upsample + mean-subtract + Mahalanobis quadratic form.
// One block per n. 224 threads (7 warps). Active t<200:
//   bg = (t&7)*4 (4 batches = 2 f32x2 pairs), dg = t>>3 (0..24), d0 = dg*4.
// IC staged via cp.async.bulk (TMA) double buffer; broadcast LDS reads.
// ---------------------------------------------------------------------------
__global__ __launch_bounds__(224) void maha_kernel(const float* __restrict__ ic) {
    __shared__ float DmT[DP][36];                // [c][b]
    __shared__ float ICs[2][CCHUNK * DP];        // 2 x 8000B
    __shared__ float dists[BB];
    __shared__ __align__(8) unsigned long long mbar_sto[2];
    const int n = blockIdx.x;
    const int tid = threadIdx.x;

    unsigned int mbar0 = (unsigned int)__cvta_generic_to_shared(&mbar_sto[0]);
    unsigned int mbar1 = (unsigned int)__cvta_generic_to_shared(&mbar_sto[1]);
    unsigned int ics0 = (unsigned int)__cvta_generic_to_shared(&ICs[0][0]);
    unsigned int ics1 = (unsigned int)__cvta_generic_to_shared(&ICs[1][0]);
    const float* icn = ic + (size_t)n * (DP * DP);

    if (tid == 0) {
        mbar_init(mbar0, 1);
        mbar_init(mbar1, 1);
        asm volatile("fence.proxy.async.shared::cta;" ::: "memory");
        mbar_expect_tx(mbar0, CCHUNK * DP * 4);
        bulk_g2s(ics0, icn, CCHUNK * DP * 4, mbar0);
    }

    // bilinear source taps (half-pixel centers, clamped)
    const int yo = n >> 6, xo = n & 63;
    float yin = (yo + 0.5f) * 0.5f - 0.5f;
    float xin = (xo + 0.5f) * 0.5f - 0.5f;
    int y0 = (int)floorf(yin), x0 = (int)floorf(xin);
    float fy = yin - (float)y0, fx = xin - (float)x0;
    int y0c = max(y0, 0), y1c = min(y0 + 1, HWI - 1);
    int x0c = max(x0, 0), x1c = min(x0 + 1, HWI - 1);
    float w00 = (1.f - fy) * (1.f - fx), w01 = (1.f - fy) * fx;
    float w10 = fy * (1.f - fx),         w11 = fy * fx;
    int p00 = y0c * HWI + x0c, p01 = y0c * HWI + x1c;
    int p10 = y1c * HWI + x0c, p11 = y1c * HWI + x1c;

    // phase 1: DmT[c][b] via float4 taps (25 c-quads x 32 b)
    const float* mt = g_meanT + (size_t)n * DP;
#pragma unroll 2
    for (int idx = tid; idx < 800; idx += 224) {
        int b = idx / 25;
        int q = idx - b * 25;
        int c = q * 4;
        const float* P = g_proj + (size_t)b * PIN * DP;
        float4 t00 = *(const float4*)&P[p00 * DP + c];
        float4 t01 = *(const float4*)&P[p01 * DP + c];
        float4 t10 = *(const float4*)&P[p10 * DP + c];
        float4 t11 = *(const float4*)&P[p11 * DP + c];
        float4 m4 = *(const float4*)&mt[c];
        DmT[c + 0][b] = w00 * t00.x + w01 * t01.x + w10 * t10.x + w11 * t11.x - m4.x;
        DmT[c + 1][b] = w00 * t00.y + w01 * t01.y + w10 * t10.y + w11 * t11.y - m4.y;
        DmT[c + 2][b] = w00 * t00.z + w01 * t01.z + w10 * t10.z + w11 * t11.z - m4.z;
        DmT[c + 3][b] = w00 * t00.w + w01 * t01.w + w10 * t10.w + w11 * t11.w - m4.w;
    }
    if (tid < BB) dists[tid] = 0.f;
    __syncthreads();

    const int bg = (tid & 7) * 4;        // batch base (0..28 step 4)
    const int d0 = (tid >> 3) * 4;       // d base (0..96)
    const bool active = tid < 200;

    unsigned long long acc[2][4];        // [b-pair j][d-component q]
#pragma unroll
    for (int j = 0; j < 2; j++)
#pragma unroll
        for (int q = 0; q < 4; q++) acc[j][q] = 0ull;

    for (int k = 0; k < NCHUNK; k++) {
        if (tid == 0 && k + 1 < NCHUNK) {
            unsigned int dst = (k + 1) & 1 ? ics1 : ics0;
            unsigned int mb = (k + 1) & 1 ? mbar1 : mbar0;
            mbar_expect_tx(mb, CCHUNK * DP * 4);
            bulk_g2s(dst, icn + (k + 1) * CCHUNK * DP, CCHUNK * DP * 4, mb);
        }
        mbar_wait(k & 1 ? mbar1 : mbar0, (k >> 1) & 1);
        if (active) {
            const float* icc = &ICs[k & 1][0] + d0;
#pragma unroll 5
            for (int cc = 0; cc < CCHUNK; cc++) {
                float4 icv = *(const float4*)(icc + cc * DP);
                unsigned long long icd[4];
                icd[0] = pack2(icv.x, icv.x);
                icd[1] = pack2(icv.y, icv.y);
                icd[2] = pack2(icv.z, icv.z);
                icd[3] = pack2(icv.w, icv.w);
                int c = k * CCHUNK + cc;
                ulonglong2 da = *(const ulonglong2*)&DmT[c][bg];
                unsigned long long dm[2] = {da.x, da.y};
#pragma unroll
                for (int j = 0; j < 2; j++)
#pragma unroll
                    for (int q = 0; q < 4; q++)
                        acc[j][q] = fma2(dm[j], icd[q], acc[j][q]);
            }
        }
        __syncthreads();
    }

    if (active) {
#pragma unroll
        for (int j = 0; j < 2; j++) {
            unsigned long long s2 = 0ull;
#pragma unroll
            for (int q = 0; q < 4; q++) {
                unsigned long long dp =
                    *(const unsigned long long*)&DmT[d0 + q][bg + 2 * j];
                s2 = fma2(acc[j][q], dp, s2);
            }
            float2 s = unpack2(s2);
            atomicAdd(&dists[bg + 2 * j], s.x);
            atomicAdd(&dists[bg + 2 * j + 1], s.y);
        }
    }
    __syncthreads();
    if (tid < BB) g_dist[(size_t)tid * NPOS + n] = dists[tid];
}

// ---------------------------------------------------------------------------
// Normalize + 4x bilinear upsample 64x64 -> 256x256 (4 outputs/thread)
// ---------------------------------------------------------------------------
__global__ void upsample_kernel(const float* __restrict__ nmin_p,
                                const float* __restrict__ nmax_p,
                                float* __restrict__ out) {
    const int b = blockIdx.y;
    const int i = blockIdx.x * blockDim.x + threadIdx.x;
    const int yo = i >> 6;
    const int xb = (i & 63) * 4;

    float yin = (yo + 0.5f) * 0.25f - 0.5f;
    int y0 = (int)floorf(yin);
    float fy = yin - (float)y0;
    int y0c = max(y0, 0), y1c = min(y0 + 1, HWF - 1);

    const float* dn = g_dist + (size_t)b * NPOS;
    const float* r0 = dn + y0c * HWF;
    const float* r1 = dn + y1c * HWF;
    float nmin = *nmin_p, nmax = *nmax_p;
    float inv = 1.f / (nmax - nmin + 1e-8f);

    float4 res;
    float* resp = (float*)&res;
#pragma unroll
    for (int k = 0; k < 4; k++) {
        int xo = xb + k;
        float xin = (xo + 0.5f) * 0.25f - 0.5f;
        int x0 = (int)floorf(xin);
        float fx = xin - (float)x0;
        int x0c = max(x0, 0), x1c = min(x0 + 1, HWF - 1);
        float v = (1.f - fy) * ((1.f - fx) * r0[x0c] + fx * r0[x1c])
                + fy * ((1.f - fx) * r1[x0c] + fx * r1[x1c]);
        resp[k] = (v - nmin) * inv;
    }
    *(float4*)&out[(size_t)b * (OHW * OHW) + yo * OHW + xb] = res;
}

// ---------------------------------------------------------------------------
extern "C" void kernel_launch(void* const* d_in, const int* in_sizes, int n_in,
                              void* d_out, int out_size) {
    (void)in_sizes; (void)n_in; (void)out_size;
    const float* combined = (const float*)d_in[0];
    const float* proj_w   = (const float*)d_in[1];
    const float* proj_b   = (const float*)d_in[2];
    const float* mean     = (const float*)d_in[3];
    const float* inv_cov  = (const float*)d_in[4];
    const float* nmin     = (const float*)d_in[5];
    const float* nmax     = (const float*)d_in[6];
    float* out = (float*)d_out;

    prep_w_kernel<<<(CC * DPAD + 255) / 256, 256>>>(proj_w);
    prep_mean_kernel<<<dim3(NPOS / 32, 4), dim3(32, 8)>>>(mean);
    proj_kernel<<<dim3(16, BB), 208>>>(combined, proj_b);
    maha_kernel<<<NPOS, 224>>>(inv_cov);
    upsample_kernel<<<dim3(OHW * OHW / (256 * 4), BB), 256>>>(nmin, nmax, out);
}